// round 6
// baseline (speedup 1.0000x reference)
#include <cuda_runtime.h>
#include <cstdint>

// MeanAggregator: out[b, :] = (1/K) * sum_k features[neigh_idx[b,k], :]
// features: [1e6, 128] fp32 (512 MB), neigh_idx: [1e5, 10] int32, out: [1e5,128] fp32.
//
// DRAM-bound random gather. Proven shape: one warp per output row, lane l owns
// float4 chunk l (32 x 16B = 512B = one row) -> every gathered row is one
// fully coalesced 512B access; K=10 fully unrolled -> 10 independent LDG.128
// front-batched per row.
//
// R6 change: persistent grid-stride loop + index prefetch. The next row's
// 10 indices are loaded BEFORE the current row's gathers issue, so the
// ~250-cycle index load fully overlaps gather latency, and 12,500 short-lived
// blocks become ~8k long-lived warps (no block churn, no per-block prologue).

#define D 128
#define KNEIGH 10

__global__ __launch_bounds__(256) void mean_agg_kernel(
    const float* __restrict__ features,
    const int* __restrict__ neigh_idx,
    float* __restrict__ out,
    int B)
{
    const int lane  = threadIdx.x & 31;
    const int warp  = (blockIdx.x * blockDim.x + threadIdx.x) >> 5;
    const int nwarp = (gridDim.x * blockDim.x) >> 5;

    int b = warp;

    // Prologue: load this row's indices (lanes 0..9).
    int my_idx = 0;
    if (b < B && lane < KNEIGH) {
        my_idx = __ldg(neigh_idx + (long long)b * KNEIGH + lane);
    }

    while (b < B) {
        const int nb = b + nwarp;

        // Prefetch next iteration's indices; overlaps with this row's gathers.
        int next_idx = 0;
        if (nb < B && lane < KNEIGH) {
            next_idx = __ldg(neigh_idx + (long long)nb * KNEIGH + lane);
        }

        float4 acc = make_float4(0.f, 0.f, 0.f, 0.f);

        #pragma unroll
        for (int k = 0; k < KNEIGH; ++k) {
            long long j = __shfl_sync(0xffffffffu, my_idx, k);
            float4 v = __ldg(reinterpret_cast<const float4*>(features + j * D) + lane);
            acc.x += v.x;
            acc.y += v.y;
            acc.z += v.z;
            acc.w += v.w;
        }

        const float inv_k = 1.0f / (float)KNEIGH;
        float4 r = make_float4(acc.x * inv_k, acc.y * inv_k,
                               acc.z * inv_k, acc.w * inv_k);
        reinterpret_cast<float4*>(out + (long long)b * D)[lane] = r;

        b = nb;
        my_idx = next_idx;
    }
}

extern "C" void kernel_launch(void* const* d_in, const int* in_sizes, int n_in,
                              void* d_out, int out_size)
{
    const float* features = (const float*)d_in[0];
    const int* neigh_idx  = (const int*)d_in[1];
    float* out            = (float*)d_out;

    const int B = in_sizes[1] / KNEIGH;   // 100,000

    // Persistent-ish: 7 blocks/SM (reg-limited occupancy cap), 148 SMs.
    // 1036 blocks x 8 warps = 8288 warps; each handles ~12 rows.
    const int grid = 148 * 7;

    mean_agg_kernel<<<grid, 256>>>(features, neigh_idx, out, B);
}

// round 7
// speedup vs baseline: 1.0865x; 1.0865x over previous
#include <cuda_runtime.h>
#include <cstdint>

// MeanAggregator: out[b, :] = (1/K) * sum_k features[neigh_idx[b,k], :]
// features: [1e6, 128] fp32 (512 MB), neigh_idx: [1e5, 10] int32, out: [1e5,128] fp32.
//
// Winning shape (R2/R5): one-shot grid, one warp per output row, lane l owns
// float4 chunk l (32 x 16B = 512B = one feature row) -> every gathered row is
// one fully coalesced 512B access; K=10 fully unrolled -> 10 independent
// LDG.128 front-batched per warp. Structural variants (2 rows/warp, persistent
// loop) all regressed; L2 policy hints neutral.
//
// R7 change: __launch_bounds__(256, 8) forces regs <= 32 so 8 blocks/SM fit
// (64 warps/SM vs 56). DRAM was only ~80% active -> more independent gather
// streams to fill the idle cycles. Traffic unchanged.

#define D 128
#define KNEIGH 10

__global__ __launch_bounds__(256, 8) void mean_agg_kernel(
    const float* __restrict__ features,
    const int* __restrict__ neigh_idx,
    float* __restrict__ out,
    int B)
{
    const int warp_global = (blockIdx.x * blockDim.x + threadIdx.x) >> 5;
    const int lane = threadIdx.x & 31;
    if (warp_global >= B) return;

    // Lanes 0..9 each load one neighbor index for this row, broadcast via shfl.
    int my_idx = 0;
    if (lane < KNEIGH) {
        my_idx = __ldg(neigh_idx + (long long)warp_global * KNEIGH + lane);
    }

    float4 acc = make_float4(0.f, 0.f, 0.f, 0.f);

    #pragma unroll
    for (int k = 0; k < KNEIGH; ++k) {
        long long j = __shfl_sync(0xffffffffu, my_idx, k);
        float4 v = __ldg(reinterpret_cast<const float4*>(features + j * D) + lane);
        acc.x += v.x;
        acc.y += v.y;
        acc.z += v.z;
        acc.w += v.w;
    }

    const float inv_k = 1.0f / (float)KNEIGH;
    float4 r = make_float4(acc.x * inv_k, acc.y * inv_k, acc.z * inv_k, acc.w * inv_k);
    reinterpret_cast<float4*>(out + (long long)warp_global * D)[lane] = r;
}

extern "C" void kernel_launch(void* const* d_in, const int* in_sizes, int n_in,
                              void* d_out, int out_size)
{
    const float* features = (const float*)d_in[0];
    const int* neigh_idx  = (const int*)d_in[1];
    float* out            = (float*)d_out;

    const int B = in_sizes[1] / KNEIGH;   // 100,000

    const int warps_per_block = 256 / 32; // 8
    const int grid = (B + warps_per_block - 1) / warps_per_block; // 12,500

    mean_agg_kernel<<<grid, 256>>>(features, neigh_idx, out, B);
}